// round 1
// baseline (speedup 1.0000x reference)
#include <cuda_runtime.h>
#include <cstdint>

// ---------------------------------------------------------------------------
// Head attention, fused:  out = softmax_causal( x * (8*Wq*Wk^T) * x^T ) * x * Wv
// B=16384 batches, T=32, D=H=64, all fp32.
// One warp per batch; lane t owns output row t.
// ---------------------------------------------------------------------------

#define BQ 6                 // batches (warps) per CTA
#define THREADS (BQ * 32)

__device__ float g_M8[64 * 64];   // M8[a][b] = 8 * sum_h Wq[a,h] * Wk[b,h]

__global__ void prep_M8(const float* __restrict__ Wk, const float* __restrict__ Wq) {
    int e = blockIdx.x * blockDim.x + threadIdx.x;
    if (e < 64 * 64) {
        int a = e >> 6, b = e & 63;
        const float* qa = Wq + a * 64;
        const float* kb = Wk + b * 64;
        float s0 = 0.f, s1 = 0.f, s2 = 0.f, s3 = 0.f;
        #pragma unroll
        for (int h = 0; h < 64; h += 4) {
            s0 = fmaf(qa[h + 0], kb[h + 0], s0);
            s1 = fmaf(qa[h + 1], kb[h + 1], s1);
            s2 = fmaf(qa[h + 2], kb[h + 2], s2);
            s3 = fmaf(qa[h + 3], kb[h + 3], s3);
        }
        g_M8[e] = 8.0f * ((s0 + s1) + (s2 + s3));
    }
}

// smem layout (floats):
//   [0, 4096)            M8s
//   [4096, 8192)         Wvs
//   per warp w at 8192 + w*3232:
//     x:  32 rows * 68 stride  (2176)
//     p:  32 rows * 33 stride  (1056)
#define XSTRIDE 68
#define PSTRIDE 33
#define WARP_FLOATS (32 * XSTRIDE + 32 * PSTRIDE)
#define SMEM_FLOATS (8192 + BQ * WARP_FLOATS)
#define SMEM_BYTES (SMEM_FLOATS * 4)

__global__ void __launch_bounds__(THREADS, 2)
attn_kernel(const float* __restrict__ X, const float* __restrict__ Wv,
            float* __restrict__ Out, int nBatch)
{
    extern __shared__ float smem[];
    float* M8s = smem;
    float* Wvs = smem + 4096;

    const int tid  = threadIdx.x;
    const int wid  = tid >> 5;
    const int lane = tid & 31;

    float* xs = smem + 8192 + wid * WARP_FLOATS;
    float* ps = xs + 32 * XSTRIDE;

    // Cooperative weight load (hot in L2 across CTAs)
    {
        const float4* s1 = (const float4*)g_M8;
        const float4* s2 = (const float4*)Wv;
        float4* d1 = (float4*)M8s;
        float4* d2 = (float4*)Wvs;
        for (int i = tid; i < 1024; i += THREADS) { d1[i] = s1[i]; d2[i] = s2[i]; }
    }
    __syncthreads();

    const int batch = blockIdx.x * BQ + wid;
    if (batch >= nBatch) return;

    // Load this warp's x[32][64] into padded smem (coalesced float4)
    {
        const float4* xg = (const float4*)(X + (size_t)batch * 2048);
        #pragma unroll
        for (int k = 0; k < 16; ++k) {
            int i = k * 32 + lane;          // 512 float4 total
            float4 v = xg[i];
            int t = i >> 4;                  // 16 float4 per row
            int c = i & 15;
            *(float4*)(xs + t * XSTRIDE + c * 4) = v;
        }
        __syncwarp();
    }

    float a64[64];   // first y (= x*M8 row), later z (= p*x row)

    // ---- Step 1: y[j] = sum_d x[t][d] * M8[d][j] ----
    #pragma unroll
    for (int j = 0; j < 64; ++j) a64[j] = 0.f;
    #pragma unroll 2
    for (int d = 0; d < 64; ++d) {
        float xv = xs[lane * XSTRIDE + d];
        const float4* mrow = (const float4*)(M8s + d * 64);
        #pragma unroll
        for (int j4 = 0; j4 < 16; ++j4) {
            float4 m = mrow[j4];
            a64[j4 * 4 + 0] = fmaf(xv, m.x, a64[j4 * 4 + 0]);
            a64[j4 * 4 + 1] = fmaf(xv, m.y, a64[j4 * 4 + 1]);
            a64[j4 * 4 + 2] = fmaf(xv, m.z, a64[j4 * 4 + 2]);
            a64[j4 * 4 + 3] = fmaf(xv, m.w, a64[j4 * 4 + 3]);
        }
    }

    // ---- Step 2: logits[s] = sum_d y[d] * x[s][d]  -> ps ----
    #pragma unroll 2
    for (int s = 0; s < 32; ++s) {
        const float4* xrow = (const float4*)(xs + s * XSTRIDE);
        float c0 = 0.f, c1 = 0.f, c2 = 0.f, c3 = 0.f;
        #pragma unroll
        for (int j4 = 0; j4 < 16; ++j4) {
            float4 xv = xrow[j4];
            c0 = fmaf(a64[j4 * 4 + 0], xv.x, c0);
            c1 = fmaf(a64[j4 * 4 + 1], xv.y, c1);
            c2 = fmaf(a64[j4 * 4 + 2], xv.z, c2);
            c3 = fmaf(a64[j4 * 4 + 3], xv.w, c3);
        }
        ps[lane * PSTRIDE + s] = (c0 + c1) + (c2 + c3);
    }

    // ---- Softmax over s <= lane (per-lane registers, causal mask) ----
    {
        float p[32];
        #pragma unroll
        for (int s = 0; s < 32; ++s) p[s] = ps[lane * PSTRIDE + s];
        float m = -3.0e38f;
        #pragma unroll
        for (int s = 0; s < 32; ++s) if (s <= lane && p[s] > m) m = p[s];
        float sum = 0.f;
        #pragma unroll
        for (int s = 0; s < 32; ++s) {
            float e = (s <= lane) ? __expf(p[s] - m) : 0.f;
            p[s] = e;
            sum += e;
        }
        float inv = 1.0f / sum;
        #pragma unroll
        for (int s = 0; s < 32; ++s) ps[lane * PSTRIDE + s] = p[s] * inv;
    }

    // ---- Step 3: z[d] = sum_s p[s] * x[s][d] ----
    #pragma unroll
    for (int j = 0; j < 64; ++j) a64[j] = 0.f;
    #pragma unroll 2
    for (int s = 0; s < 32; ++s) {
        float pv = ps[lane * PSTRIDE + s];
        const float4* xrow = (const float4*)(xs + s * XSTRIDE);
        #pragma unroll
        for (int j4 = 0; j4 < 16; ++j4) {
            float4 xv = xrow[j4];
            a64[j4 * 4 + 0] = fmaf(pv, xv.x, a64[j4 * 4 + 0]);
            a64[j4 * 4 + 1] = fmaf(pv, xv.y, a64[j4 * 4 + 1]);
            a64[j4 * 4 + 2] = fmaf(pv, xv.z, a64[j4 * 4 + 2]);
            a64[j4 * 4 + 3] = fmaf(pv, xv.w, a64[j4 * 4 + 3]);
        }
    }

    // ---- Step 4: out[h] = sum_d z[d] * Wv[d][h] ----
    float* outp = Out + ((size_t)batch * 32 + lane) * 64;
    #pragma unroll 1
    for (int h4 = 0; h4 < 16; ++h4) {
        float o0 = 0.f, o1 = 0.f, o2 = 0.f, o3 = 0.f;
        #pragma unroll
        for (int d = 0; d < 64; ++d) {
            float4 wv = *(const float4*)(Wvs + d * 64 + h4 * 4);
            float zv = a64[d];
            o0 = fmaf(zv, wv.x, o0);
            o1 = fmaf(zv, wv.y, o1);
            o2 = fmaf(zv, wv.z, o2);
            o3 = fmaf(zv, wv.w, o3);
        }
        float4 o = make_float4(o0, o1, o2, o3);
        *(float4*)(outp + h4 * 4) = o;
    }
}

extern "C" void kernel_launch(void* const* d_in, const int* in_sizes, int n_in,
                              void* d_out, int out_size)
{
    const float* X  = (const float*)d_in[0];   // x  [B,32,64]
    const float* Wk = (const float*)d_in[1];   // Wk [64,64]
    const float* Wq = (const float*)d_in[2];   // Wq [64,64]
    const float* Wv = (const float*)d_in[3];   // Wv [64,64]
    float* Out = (float*)d_out;

    const int nBatch = in_sizes[0] / (32 * 64);

    static bool attr_set = false;
    if (!attr_set) {
        cudaFuncSetAttribute(attn_kernel,
                             cudaFuncAttributeMaxDynamicSharedMemorySize,
                             SMEM_BYTES);
        attr_set = true;
    }

    prep_M8<<<16, 256>>>(Wk, Wq);

    int grid = (nBatch + BQ - 1) / BQ;
    attn_kernel<<<grid, THREADS, SMEM_BYTES>>>(X, Wv, Out, nBatch);
}

// round 5
// speedup vs baseline: 3.7526x; 3.7526x over previous
#include <cuda_runtime.h>
#include <cuda_fp16.h>
#include <cstdint>

// ============================================================================
// Fused attention via warp-level mma.sync (sm_100 base target; no tcgen05).
//   out = softmax_causal( X * (8 Wq Wk^T) * X^T ) * X * Wv
// B=16384 batches, T=32, D=H=64, fp32 I/O. One warp per batch.
// All GEMMs: mma.sync.m16n8k16 fp16 x fp16 -> fp32, with hi/lo fp16 splits.
// Intermediates (Y, P, Z) never leave registers: D-fragment layout == A-fragment
// layout, so conversions are pure register ops.
// ============================================================================

#define WARPS   8
#define THREADS (WARPS * 32)
#define LDW     36            // u32 words per smem row (72 halves, 144 B)

// smem word offsets
#define W_MH   0
#define W_ML   (64 * LDW)
#define W_WVH  (2 * 64 * LDW)
#define W_WVL  (3 * 64 * LDW)
#define W_X    (4 * 64 * LDW)              // per-warp region starts here
#define W_PER_WARP (2 * 32 * LDW)          // Xh + Xl
#define SMEM_WORDS (W_X + WARPS * W_PER_WARP)
#define SMEM_BYTES (SMEM_WORDS * 4)

// ---- fp16-split weight tables (prepared once per launch) ----
__device__ __half g_Mh[4096], g_Ml[4096], g_Wvh[4096], g_Wvl[4096];

__global__ void prep_weights(const float* __restrict__ Wk, const float* __restrict__ Wq,
                             const float* __restrict__ Wv) {
    int e = blockIdx.x * blockDim.x + threadIdx.x;
    if (e >= 4096) return;
    int j = e >> 6, d = e & 63;            // row j (=n), col d (=k)

    // B_M[j][d] = M8[d][j] = 8 * sum_h Wq[d,h] * Wk[j,h]
    float s = 0.f;
    #pragma unroll
    for (int h = 0; h < 64; ++h) s = fmaf(Wq[d * 64 + h], Wk[j * 64 + h], s);
    s *= 8.0f;
    __half mh = __float2half_rn(s);
    g_Mh[e] = mh;
    g_Ml[e] = __float2half_rn(s - __half2float(mh));

    // B_Wv[h][d] = Wv[d][h]  (j plays the role of h)
    float w = Wv[d * 64 + j];
    __half wh = __float2half_rn(w);
    g_Wvh[e] = wh;
    g_Wvl[e] = __float2half_rn(w - __half2float(wh));
}

// ---- helpers ----
#define MMA(d, a, b) asm volatile( \
    "mma.sync.aligned.m16n8k16.row.col.f32.f16.f16.f32 " \
    "{%0,%1,%2,%3}, {%4,%5,%6,%7}, {%8,%9}, {%0,%1,%2,%3};" \
    : "+f"((d)[0]), "+f"((d)[1]), "+f"((d)[2]), "+f"((d)[3]) \
    : "r"((a)[0]), "r"((a)[1]), "r"((a)[2]), "r"((a)[3]), \
      "r"((b)[0]), "r"((b)[1]))

__device__ __forceinline__ void split2(float a, float b, uint32_t& h, uint32_t& l) {
    __half2 hh = __floats2half2_rn(a, b);
    float2 hf = __half22float2(hh);
    __half2 ll = __floats2half2_rn(a - hf.x, b - hf.y);
    h = *(uint32_t*)&hh;
    l = *(uint32_t*)&ll;
}
__device__ __forceinline__ uint32_t pack2(float a, float b) {
    __half2 hh = __floats2half2_rn(a, b);
    return *(uint32_t*)&hh;
}
__device__ __forceinline__ uint32_t packh(__half a, __half b) {
    __half2 hh = __halves2half2(a, b);
    return *(uint32_t*)&hh;
}

__global__ void __launch_bounds__(THREADS, 2)
attn_kernel(const float* __restrict__ X, float* __restrict__ Out, int nBatch)
{
    extern __shared__ uint32_t sw[];
    const int tid  = threadIdx.x;
    const int wid  = tid >> 5;
    const int lane = tid & 31;
    const int g = lane >> 2;      // group (row) id 0..7
    const int t = lane & 3;       // thread-in-group (col pair) id 0..3

    // ---- weights -> padded smem (shared by all warps) ----
    {
        const uint32_t* src[4] = { (const uint32_t*)g_Mh,  (const uint32_t*)g_Ml,
                                   (const uint32_t*)g_Wvh, (const uint32_t*)g_Wvl };
        #pragma unroll
        for (int arr = 0; arr < 4; ++arr)
            for (int i = tid; i < 2048; i += THREADS) {
                int r = i >> 5, c = i & 31;           // 32 words per 64-half row
                sw[arr * 64 * LDW + r * LDW + c] = src[arr][i];
            }
    }
    __syncthreads();

    const int batch = blockIdx.x * WARPS + wid;
    if (batch >= nBatch) return;

    uint32_t* xh = sw + W_X + wid * W_PER_WARP;
    uint32_t* xl = xh + 32 * LDW;

    // ---- load X (coalesced) + hi/lo fp16 split into smem ----
    {
        const float4* xg = (const float4*)(X + (size_t)batch * 2048);
        #pragma unroll
        for (int it = 0; it < 16; ++it) {
            int i = it * 32 + lane;          // 512 float4
            float4 v = xg[i];
            int r = i >> 4, c = i & 15;      // row r, float4 col c -> words c*2, c*2+1
            uint32_t h0, l0, h1, l1;
            split2(v.x, v.y, h0, l0);
            split2(v.z, v.w, h1, l1);
            xh[r * LDW + c * 2]     = h0;
            xh[r * LDW + c * 2 + 1] = h1;
            xl[r * LDW + c * 2]     = l0;
            xl[r * LDW + c * 2 + 1] = l1;
        }
        __syncwarp();
    }

    // ---- resident Xh A-fragments: XA[m][kk] covers rows m*16.., k-cols kk*16.. ----
    uint32_t XA[2][4][4];
    #pragma unroll
    for (int m = 0; m < 2; ++m)
        #pragma unroll
        for (int kk = 0; kk < 4; ++kk) {
            int base = (g + m * 16) * LDW + kk * 8 + t;
            XA[m][kk][0] = xh[base];
            XA[m][kk][1] = xh[base + 8 * LDW];
            XA[m][kk][2] = xh[base + 4];
            XA[m][kk][3] = xh[base + 8 * LDW + 4];
        }

    // ---- logits accumulator L[m][ns][4] : rows m*16.., cols ns*8.. ----
    float L[2][4][4];
    #pragma unroll
    for (int m = 0; m < 2; ++m)
        #pragma unroll
        for (int n = 0; n < 4; ++n)
            #pragma unroll
            for (int r = 0; r < 4; ++r) L[m][n][r] = 0.f;

    // ================= G1 + G2 fused over d-blocks of 16 =================
    #pragma unroll
    for (int kd = 0; kd < 4; ++kd) {
        // G1: Y block (rows 32, d-cols kd*16..kd*16+15) = X * M8'
        float ya[2][2][4];
        #pragma unroll
        for (int m = 0; m < 2; ++m)
            #pragma unroll
            for (int j = 0; j < 2; ++j)
                #pragma unroll
                for (int r = 0; r < 4; ++r) ya[m][j][r] = 0.f;

        #pragma unroll
        for (int kk = 0; kk < 4; ++kk) {
            uint32_t bh[2][2], bl[2][2];
            #pragma unroll
            for (int j = 0; j < 2; ++j) {
                int wb = ((2 * kd + j) * 8 + g) * LDW + kk * 8 + t;
                bh[j][0] = sw[W_MH + wb]; bh[j][1] = sw[W_MH + wb + 4];
                bl[j][0] = sw[W_ML + wb]; bl[j][1] = sw[W_ML + wb + 4];
            }
            #pragma unroll
            for (int m = 0; m < 2; ++m) {
                uint32_t xlf[4];
                int base = (g + m * 16) * LDW + kk * 8 + t;
                xlf[0] = xl[base];
                xlf[1] = xl[base + 8 * LDW];
                xlf[2] = xl[base + 4];
                xlf[3] = xl[base + 8 * LDW + 4];
                #pragma unroll
                for (int j = 0; j < 2; ++j) {
                    MMA(ya[m][j], XA[m][kk], bh[j]);   // Xh * Mh
                    MMA(ya[m][j], XA[m][kk], bl[j]);   // Xh * Ml
                    MMA(ya[m][j], xlf,       bh[j]);   // Xl * Mh
                }
            }
        }

        // convert Y block (f32) -> A fragments (hi/lo) in registers
        uint32_t yh[2][4], yl2[2][4];
        #pragma unroll
        for (int m = 0; m < 2; ++m) {
            split2(ya[m][0][0], ya[m][0][1], yh[m][0], yl2[m][0]);
            split2(ya[m][0][2], ya[m][0][3], yh[m][1], yl2[m][1]);
            split2(ya[m][1][0], ya[m][1][1], yh[m][2], yl2[m][2]);
            split2(ya[m][1][2], ya[m][1][3], yh[m][3], yl2[m][3]);
        }

        // G2: logits += Y_block * X^T_block   (B = X[s][d] as [n][k])
        #pragma unroll
        for (int ns = 0; ns < 4; ++ns) {
            int wb = (ns * 8 + g) * LDW + kd * 8 + t;
            uint32_t bh2[2] = { xh[wb], xh[wb + 4] };
            uint32_t bl3[2] = { xl[wb], xl[wb + 4] };
            #pragma unroll
            for (int m = 0; m < 2; ++m) {
                MMA(L[m][ns], yh[m],  bh2);
                MMA(L[m][ns], yh[m],  bl3);
                MMA(L[m][ns], yl2[m], bh2);
            }
        }
    }

    // ================= causal softmax (registers + quad shuffles) =================
    #pragma unroll
    for (int m = 0; m < 2; ++m)
        #pragma unroll
        for (int hh = 0; hh < 2; ++hh) {
            int r = g + m * 16 + hh * 8;
            float vmax = -3.0e38f;
            #pragma unroll
            for (int n = 0; n < 4; ++n) {
                int c0 = n * 8 + t * 2;
                float v0 = L[m][n][hh * 2 + 0], v1 = L[m][n][hh * 2 + 1];
                if (c0     <= r && v0 > vmax) vmax = v0;
                if (c0 + 1 <= r && v1 > vmax) vmax = v1;
            }
            vmax = fmaxf(vmax, __shfl_xor_sync(0xffffffffu, vmax, 1));
            vmax = fmaxf(vmax, __shfl_xor_sync(0xffffffffu, vmax, 2));
            float sum = 0.f;
            #pragma unroll
            for (int n = 0; n < 4; ++n) {
                int c0 = n * 8 + t * 2;
                float e0 = (c0     <= r) ? __expf(L[m][n][hh * 2 + 0] - vmax) : 0.f;
                float e1 = (c0 + 1 <= r) ? __expf(L[m][n][hh * 2 + 1] - vmax) : 0.f;
                L[m][n][hh * 2 + 0] = e0;
                L[m][n][hh * 2 + 1] = e1;
                sum += e0 + e1;
            }
            sum += __shfl_xor_sync(0xffffffffu, sum, 1);
            sum += __shfl_xor_sync(0xffffffffu, sum, 2);
            float inv = 1.0f / sum;
            #pragma unroll
            for (int n = 0; n < 4; ++n) {
                L[m][n][hh * 2 + 0] *= inv;
                L[m][n][hh * 2 + 1] *= inv;
            }
        }

    // P A-fragments (fp16, hi only): PF[m][ks] covers rows m*16.., s-cols ks*16..
    uint32_t PF[2][2][4];
    #pragma unroll
    for (int m = 0; m < 2; ++m)
        #pragma unroll
        for (int ks = 0; ks < 2; ++ks) {
            PF[m][ks][0] = pack2(L[m][2 * ks][0],     L[m][2 * ks][1]);
            PF[m][ks][1] = pack2(L[m][2 * ks][2],     L[m][2 * ks][3]);
            PF[m][ks][2] = pack2(L[m][2 * ks + 1][0], L[m][2 * ks + 1][1]);
            PF[m][ks][3] = pack2(L[m][2 * ks + 1][2], L[m][2 * ks + 1][3]);
        }

    // ================= G3: Z = P * X  (B[k=s][n=d] = X[s][d], col-major frags
    //                   built from two LDS.U16 + pack) =================
    uint32_t ZF[2][4][4];
    const __half* xhh = (const __half*)xh;
    const __half* xlh = (const __half*)xl;
    #pragma unroll
    for (int nd = 0; nd < 8; ++nd) {
        float za[2][4];
        #pragma unroll
        for (int m = 0; m < 2; ++m)
            #pragma unroll
            for (int r = 0; r < 4; ++r) za[m][r] = 0.f;

        #pragma unroll
        for (int ks = 0; ks < 2; ++ks) {
            int r0 = ks * 16 + t * 2;           // k rows (s)
            int c  = nd * 8 + g;                // n col (d)
            uint32_t bh4[2], bl4[2];
            bh4[0] = packh(xhh[r0 * 72 + c],       xhh[(r0 + 1) * 72 + c]);
            bh4[1] = packh(xhh[(r0 + 8) * 72 + c], xhh[(r0 + 9) * 72 + c]);
            bl4[0] = packh(xlh[r0 * 72 + c],       xlh[(r0 + 1) * 72 + c]);
            bl4[1] = packh(xlh[(r0 + 8) * 72 + c], xlh[(r0 + 9) * 72 + c]);
            #pragma unroll
            for (int m = 0; m < 2; ++m) {
                MMA(za[m], PF[m][ks], bh4);
                MMA(za[m], PF[m][ks], bl4);
            }
        }
        // fold Z block into A fragments for G4
        int kk = nd >> 1;
        #pragma unroll
        for (int m = 0; m < 2; ++m) {
            if ((nd & 1) == 0) {
                ZF[m][kk][0] = pack2(za[m][0], za[m][1]);
                ZF[m][kk][1] = pack2(za[m][2], za[m][3]);
            } else {
                ZF[m][kk][2] = pack2(za[m][0], za[m][1]);
                ZF[m][kk][3] = pack2(za[m][2], za[m][3]);
            }
        }
    }

    // ================= G4: out = Z * Wv'  (+ direct stores) =================
    float* outp = Out + (size_t)batch * 2048;
    #pragma unroll
    for (int nh = 0; nh < 8; ++nh) {
        float oa[2][4];
        #pragma unroll
        for (int m = 0; m < 2; ++m)
            #pragma unroll
            for (int r = 0; r < 4; ++r) oa[m][r] = 0.f;

        #pragma unroll
        for (int kk = 0; kk < 4; ++kk) {
            int wb = (nh * 8 + g) * LDW + kk * 8 + t;
            uint32_t bh5[2] = { sw[W_WVH + wb], sw[W_WVH + wb + 4] };
            uint32_t bl5[2] = { sw[W_WVL + wb], sw[W_WVL + wb + 4] };
            #pragma unroll
            for (int m = 0; m < 2; ++m) {
                MMA(oa[m], ZF[m][kk], bh5);
                MMA(oa[m], ZF[m][kk], bl5);
            }
        }
        #pragma unroll
        for (int m = 0; m < 2; ++m) {
            int r = g + m * 16;
            *(float2*)(outp + r * 64 + nh * 8 + t * 2)       = make_float2(oa[m][0], oa[m][1]);
            *(float2*)(outp + (r + 8) * 64 + nh * 8 + t * 2) = make_float2(oa[m][2], oa[m][3]);
        }
    }
}

extern "C" void kernel_launch(void* const* d_in, const int* in_sizes, int n_in,
                              void* d_out, int out_size)
{
    const float* X  = (const float*)d_in[0];
    const float* Wk = (const float*)d_in[1];
    const float* Wq = (const float*)d_in[2];
    const float* Wv = (const float*)d_in[3];
    float* Out = (float*)d_out;

    const int nBatch = in_sizes[0] / 2048;

    // Unconditional (no static guards — harness determinism rule); idempotent.
    cudaFuncSetAttribute(attn_kernel,
                         cudaFuncAttributeMaxDynamicSharedMemorySize, SMEM_BYTES);

    prep_weights<<<16, 256>>>(Wk, Wq, Wv);

    int grid = (nBatch + WARPS - 1) / WARPS;
    attn_kernel<<<grid, THREADS, SMEM_BYTES>>>(X, Out, nBatch);
}